// round 5
// baseline (speedup 1.0000x reference)
#include <cuda_runtime.h>
#include <cuda_fp16.h>
#include <cstdint>

#define Hdim 256
#define Bdim 2048
#define Tdim 512
#define Vdim 64
#define NB   16          // batches per CTA -> 128 CTAs
#define NTH  512         // 16 warps, one m16 tile each
#define HROW 24          // padded hT row stride in halfs (48B): conflict-free ldmatrix

// ---- shared memory layout (bytes) ----
// Phase 1 (prologue staging, transient):
//   [0, 131072)       Whh fp16 [256][256]   (then dead)
//   [65536, 131072)   embT f32 [256][64]    (phase 1b, after afrag built)
// Phase 2 (steady state):
#define SM_P     0         // P[64][256] f32: 64 KiB
#define SM_H0    65536     // hT buf0: 256 rows x 24 halfs = 12288 B
#define SM_H1    77824     // hT buf1: 12288 B
#define SM_TOK   90112     // tokens [16][512] int: 32 KiB  (ends 122880)
#define SM_EMBT  65536     // embT staging (phase 1b; dead before H0 init)
#define SMEM_TOTAL 131072

// ---------------------------------------------------------------------------
__device__ __forceinline__ uint32_t smem_u32(const void* p) {
    uint32_t a;
    asm("{ .reg .u64 t; cvta.to.shared.u64 t, %1; cvt.u32.u64 %0, t; }"
        : "=r"(a) : "l"(p));
    return a;
}
__device__ __forceinline__ float sigmoidf(float x) {
    return __fdividef(1.0f, 1.0f + __expf(-x));
}
__device__ __forceinline__ void ffma2(unsigned long long& d,
                                      unsigned long long a, unsigned long long b) {
    asm("fma.rn.f32x2 %0, %1, %2, %0;" : "+l"(d) : "l"(a), "l"(b));
}
__device__ __forceinline__ unsigned long long pack2(float lo, float hi) {
    unsigned long long r;
    asm("mov.b64 %0, {%1, %2};" : "=l"(r) : "f"(lo), "f"(hi));
    return r;
}
__device__ __forceinline__ void mma16816(float* d, const uint32_t* a,
                                         uint32_t b0, uint32_t b1) {
    asm volatile(
        "mma.sync.aligned.m16n8k16.row.col.f32.f16.f16.f32 "
        "{%0,%1,%2,%3}, {%4,%5,%6,%7}, {%8,%9}, {%0,%1,%2,%3};"
        : "+f"(d[0]), "+f"(d[1]), "+f"(d[2]), "+f"(d[3])
        : "r"(a[0]), "r"(a[1]), "r"(a[2]), "r"(a[3]), "r"(b0), "r"(b1));
}
__device__ __forceinline__ void ldmx4t(uint32_t& r0, uint32_t& r1,
                                       uint32_t& r2, uint32_t& r3, uint32_t addr) {
    asm volatile(
        "ldmatrix.sync.aligned.m8n8.x4.trans.shared.b16 {%0,%1,%2,%3}, [%4];"
        : "=r"(r0), "=r"(r1), "=r"(r2), "=r"(r3) : "r"(addr));
}

// ---------------------------------------------------------------------------
// Persistent RNN: one CTA owns 16 batch chains for all 512 steps.
// Warp w computes output rows [16w, 16w+16) (one m16n16 tile via 2x n8 MMA).
// Wh fragments (fp16) are register-resident for the whole kernel.
// ---------------------------------------------------------------------------
__global__ __launch_bounds__(NTH, 1)
void k_rnn(const int* __restrict__ tokens,
           const float* __restrict__ h0,
           const float* __restrict__ emb,
           const float* __restrict__ W,
           const float* __restrict__ bias,
           float* __restrict__ out) {
    extern __shared__ char smem[];
    const uint32_t sbase = smem_u32(smem);
    float* Psm     = (float*)(smem + SM_P);
    int*   toksAll = (int*)(smem + SM_TOK);

    const int tid  = threadIdx.x;
    const int wid  = tid >> 5;
    const int lane = tid & 31;
    const int g    = lane >> 2;     // 0..7
    const int r    = lane & 3;      // 0..3
    const int bbase = blockIdx.x * NB;

    // ============== Prologue ==============
    // (1) stage Wh fp16 [o][k] at smem+0 (128 KiB, transient)
    {
        __half* Whh = (__half*)smem;
        for (int idx = tid; idx < Hdim * Hdim; idx += NTH) {
            int o = idx >> 8, k = idx & 255;
            Whh[(size_t)o * Hdim + k] =
                __float2half_rn(W[(size_t)o * (2 * Hdim) + Hdim + k]);
        }
    }
    __syncthreads();
    // (2) register-resident A fragments for this warp's m16 tile
    uint32_t afrag[16][4];
    {
        const __half* Whh = (const __half*)smem;
        int row0 = wid * 16 + g;
        int row1 = row0 + 8;
#pragma unroll
        for (int c = 0; c < 16; ++c) {
            int k0 = c * 16 + r * 2;
            afrag[c][0] = *(const uint32_t*)&Whh[(size_t)row0 * Hdim + k0];
            afrag[c][1] = *(const uint32_t*)&Whh[(size_t)row1 * Hdim + k0];
            afrag[c][2] = *(const uint32_t*)&Whh[(size_t)row0 * Hdim + k0 + 8];
            afrag[c][3] = *(const uint32_t*)&Whh[(size_t)row1 * Hdim + k0 + 8];
        }
    }
    __syncthreads();
    // (3) stage embT f32 [k][v] at SM_EMBT (Whh upper half now dead)
    {
        float* embT = (float*)(smem + SM_EMBT);
        for (int idx = tid; idx < Vdim * Hdim; idx += NTH) {
            int k = idx >> 6, v = idx & 63;
            embT[idx] = emb[(size_t)v * Hdim + k];
        }
    }
    __syncthreads();
    // (4) P[v][o] = bias[o] + emb[v,:]·Wx[o,:]; thread owns (o = tid&255, 2 v-groups)
    {
        const float* embT = (const float*)(smem + SM_EMBT);
        const int o = tid & 255;
        const int vg0 = (tid >> 8) * 2;
        const float bo = bias[o];
        const float4* wrow = (const float4*)(W + (size_t)o * (2 * Hdim));
        for (int vg = vg0; vg < vg0 + 2; ++vg) {
            unsigned long long acc[8];
#pragma unroll
            for (int i = 0; i < 8; ++i) acc[i] = pack2(0.f, 0.f);
            for (int k4 = 0; k4 < Hdim / 4; ++k4) {
                float4 wv = wrow[k4];
#pragma unroll
                for (int kk = 0; kk < 4; ++kk) {
                    int k = k4 * 4 + kk;
                    float w = (kk == 0) ? wv.x : (kk == 1) ? wv.y : (kk == 2) ? wv.z : wv.w;
                    unsigned long long wpair = pack2(w, w);
                    const ulonglong2* ep =
                        (const ulonglong2*)(embT + (size_t)k * 64 + vg * 16);
                    ulonglong2 e0 = ep[0], e1 = ep[1], e2 = ep[2], e3 = ep[3];
                    ffma2(acc[0], wpair, e0.x); ffma2(acc[1], wpair, e0.y);
                    ffma2(acc[2], wpair, e1.x); ffma2(acc[3], wpair, e1.y);
                    ffma2(acc[4], wpair, e2.x); ffma2(acc[5], wpair, e2.y);
                    ffma2(acc[6], wpair, e3.x); ffma2(acc[7], wpair, e3.y);
                }
            }
#pragma unroll
            for (int i = 0; i < 8; ++i) {
                float lo = __uint_as_float((uint32_t)(acc[i] & 0xffffffffu));
                float hi = __uint_as_float((uint32_t)(acc[i] >> 32));
                int v0 = vg * 16 + 2 * i;
                Psm[(size_t)v0 * Hdim + o]       = bo + lo;
                Psm[(size_t)(v0 + 1) * Hdim + o] = bo + hi;
            }
        }
    }
    __syncthreads();
    // (5) init hT buf0 (fp16, padded rows) + preload the full token block
    {
        __half* hT0 = (__half*)(smem + SM_H0);
        for (int idx = tid; idx < NB * Hdim; idx += NTH) {
            int b = idx >> 8, k = idx & 255;
            hT0[(size_t)k * HROW + b] =
                __float2half_rn(h0[(size_t)(bbase + b) * Hdim + k]);
        }
        for (int idx = tid; idx < NB * Tdim; idx += NTH) {
            int b = idx >> 9, t = idx & 511;
            toksAll[idx] = tokens[(size_t)(bbase + b) * Tdim + t];
        }
    }
    __syncthreads();

    // ldmatrix per-lane address offset within a buffer (x4.trans):
    // m0=k[0:8)/n0, m1=k[8:16)/n0, m2=k[0:8)/n8, m3=k[8:16)/n8
    const int klocal = lane & 7;
    const int sel    = lane >> 3;
    const uint32_t ldm_off =
        (uint32_t)(((sel & 1) * 8 + klocal) * (HROW * 2) + ((sel >> 1) * 8) * 2);

    const int o_lo = wid * 16 + g;
    const int o_hi = o_lo + 8;
    float* const outbase = out + (size_t)bbase * Hdim;

    // ============== Recurrent loop ==============
    for (int t = 0; t < Tdim; ++t) {
        // --- token + P-table preloads (independent of MMA; hide under HMMA) ---
        const int b0 = 2 * r,     b1 = b0 + 1;       // ni = 0
        const int b2 = 8 + 2 * r, b3 = b2 + 1;       // ni = 1
        int tk0 = toksAll[b0 * Tdim + t];
        int tk1 = toksAll[b1 * Tdim + t];
        int tk2 = toksAll[b2 * Tdim + t];
        int tk3 = toksAll[b3 * Tdim + t];
        float p00 = Psm[(size_t)tk0 * Hdim + o_lo];
        float p01 = Psm[(size_t)tk1 * Hdim + o_lo];
        float p02 = Psm[(size_t)tk0 * Hdim + o_hi];
        float p03 = Psm[(size_t)tk1 * Hdim + o_hi];
        float p10 = Psm[(size_t)tk2 * Hdim + o_lo];
        float p11 = Psm[(size_t)tk3 * Hdim + o_lo];
        float p12 = Psm[(size_t)tk2 * Hdim + o_hi];
        float p13 = Psm[(size_t)tk3 * Hdim + o_hi];

        const uint32_t rbuf = sbase + ((t & 1) ? SM_H1 : SM_H0) + ldm_off;

        float d[2][4];
#pragma unroll
        for (int ni = 0; ni < 2; ++ni)
#pragma unroll
            for (int i = 0; i < 4; ++i) d[ni][i] = 0.0f;

#pragma unroll
        for (int c = 0; c < 16; ++c) {
            uint32_t q0, q1, q2, q3;
            ldmx4t(q0, q1, q2, q3, rbuf + (uint32_t)c * (16 * HROW * 2));
            mma16816(d[0], afrag[c], q0, q1);
            mma16816(d[1], afrag[c], q2, q3);
        }

        // --- epilogue: x = D + P; h' = sigmoid(x); store out + hT_next ---
        __half* wT = (__half*)(smem + ((t & 1) ? SM_H0 : SM_H1));
        float* outp = outbase + (size_t)t * (Bdim * Hdim);

        float s00 = sigmoidf(d[0][0] + p00);
        float s01 = sigmoidf(d[0][1] + p01);
        float s02 = sigmoidf(d[0][2] + p02);
        float s03 = sigmoidf(d[0][3] + p03);
        float s10 = sigmoidf(d[1][0] + p10);
        float s11 = sigmoidf(d[1][1] + p11);
        float s12 = sigmoidf(d[1][2] + p12);
        float s13 = sigmoidf(d[1][3] + p13);

        outp[(size_t)b0 * Hdim + o_lo] = s00;
        outp[(size_t)b1 * Hdim + o_lo] = s01;
        outp[(size_t)b0 * Hdim + o_hi] = s02;
        outp[(size_t)b1 * Hdim + o_hi] = s03;
        outp[(size_t)b2 * Hdim + o_lo] = s10;
        outp[(size_t)b3 * Hdim + o_lo] = s11;
        outp[(size_t)b2 * Hdim + o_hi] = s12;
        outp[(size_t)b3 * Hdim + o_hi] = s13;

        *(__half2*)&wT[(size_t)o_lo * HROW + b0] = __floats2half2_rn(s00, s01);
        *(__half2*)&wT[(size_t)o_hi * HROW + b0] = __floats2half2_rn(s02, s03);
        *(__half2*)&wT[(size_t)o_lo * HROW + b2] = __floats2half2_rn(s10, s11);
        *(__half2*)&wT[(size_t)o_hi * HROW + b2] = __floats2half2_rn(s12, s13);

        __syncthreads();
    }
}

// ---------------------------------------------------------------------------
// Harness entry.
// Inputs: tokens(i32 2048x512), h0(f32 2048x256), emb(f32 64x256),
//         W(f32 256x512), b(f32 256).  Output: f32 (512,2048,256)
// ---------------------------------------------------------------------------
extern "C" void kernel_launch(void* const* d_in, const int* in_sizes, int n_in,
                              void* d_out, int out_size) {
    const int*   tokens = (const int*)d_in[0];
    const float* h0     = (const float*)d_in[1];
    const float* emb    = (const float*)d_in[2];
    const float* W      = (const float*)d_in[3];
    const float* bias   = (const float*)d_in[4];
    float*       out    = (float*)d_out;
    (void)in_sizes; (void)n_in; (void)out_size;

    cudaFuncSetAttribute(k_rnn, cudaFuncAttributeMaxDynamicSharedMemorySize, SMEM_TOTAL);
    k_rnn<<<Bdim / NB, NTH, SMEM_TOTAL>>>(tokens, h0, emb, W, bias, out);
}

// round 6
// speedup vs baseline: 1.0082x; 1.0082x over previous
#include <cuda_runtime.h>
#include <cuda_fp16.h>
#include <cstdint>

#define Hdim 256
#define Bdim 2048
#define Tdim 512
#define Vdim 64
#define NB   16          // batches per CTA -> 128 CTAs
#define NTH  256         // 8 warps
#define HSTR 264         // h row stride in halfs (528B): rows 4 banks apart
#define PSTR 266         // P row stride in floats (!= 0 mod 32)
#define ESTR 68          // embT row stride in floats (16B-aligned rows)

// ---- shared memory layout (bytes) ----
#define SM_P    0                      // P[64][PSTR] f32 = 68096
#define SM_H0   68096                  // h buf0: 16 x 264 halfs = 8448
#define SM_H1   76544                  // h buf1: 8448
#define SM_TOK  84992                  // tokens [512][16] int = 32768 (end 117760)
#define SM_EMBT 117760                 // transient embT f32 [256][ESTR] = 69632
#define SMEM_TOTAL (117760 + 69632)    // 187392

// ---------------------------------------------------------------------------
__device__ __forceinline__ uint32_t smem_u32(const void* p) {
    uint32_t a;
    asm("{ .reg .u64 t; cvta.to.shared.u64 t, %1; cvt.u32.u64 %0, t; }"
        : "=r"(a) : "l"(p));
    return a;
}
__device__ __forceinline__ float sigmoidf(float x) {
    return __fdividef(1.0f, 1.0f + __expf(-x));
}
__device__ __forceinline__ void ffma2(unsigned long long& d,
                                      unsigned long long a, unsigned long long b) {
    asm("fma.rn.f32x2 %0, %1, %2, %0;" : "+l"(d) : "l"(a), "l"(b));
}
__device__ __forceinline__ unsigned long long pack2(float lo, float hi) {
    unsigned long long r;
    asm("mov.b64 %0, {%1, %2};" : "=l"(r) : "f"(lo), "f"(hi));
    return r;
}
// m16n8k16 row.col f32=f16*f16+f32; A = h (M=batches), B = WhT (N=outputs)
__device__ __forceinline__ void mma16816(float* d, const uint32_t* a,
                                         uint32_t b0, uint32_t b1) {
    asm volatile(
        "mma.sync.aligned.m16n8k16.row.col.f32.f16.f16.f32 "
        "{%0,%1,%2,%3}, {%4,%5,%6,%7}, {%8,%9}, {%0,%1,%2,%3};"
        : "+f"(d[0]), "+f"(d[1]), "+f"(d[2]), "+f"(d[3])
        : "r"(a[0]), "r"(a[1]), "r"(a[2]), "r"(a[3]), "r"(b0), "r"(b1));
}
// non-transposed x4 ldmatrix (A row-major m16k16 fragments)
__device__ __forceinline__ void ldmx4(uint32_t& r0, uint32_t& r1,
                                      uint32_t& r2, uint32_t& r3, uint32_t addr) {
    asm volatile(
        "ldmatrix.sync.aligned.m8n8.x4.shared.b16 {%0,%1,%2,%3}, [%4];"
        : "=r"(r0), "=r"(r1), "=r"(r2), "=r"(r3) : "r"(addr));
}

// ---------------------------------------------------------------------------
// Persistent RNN: CTA owns 16 batch chains for 512 steps.
// D[16 batch, 256 out] = h[16,256] x WhT. Warp w owns outputs [32w, 32w+32)
// (4 n8 tiles); WhT fragments register-resident (128 regs). h (A operand)
// read via 16 ldmatrix.x4 per warp per step from double-buffered smem.
// Accumulators initialized with P[token][o] (exact fp32 xproj+bias).
// ---------------------------------------------------------------------------
__global__ __launch_bounds__(NTH, 1)
void k_rnn(const int* __restrict__ tokens,
           const float* __restrict__ h0,
           const float* __restrict__ emb,
           const float* __restrict__ W,
           const float* __restrict__ bias,
           float* __restrict__ out) {
    extern __shared__ char smem[];
    const uint32_t sbase = smem_u32(smem);
    float* Psm  = (float*)(smem + SM_P);
    int*   toks = (int*)(smem + SM_TOK);

    const int tid  = threadIdx.x;
    const int wid  = tid >> 5;
    const int lane = tid & 31;
    const int g    = lane >> 2;     // 0..7
    const int r    = lane & 3;      // 0..3
    const int bbase = blockIdx.x * NB;

    // ============== Prologue ==============
    // (1) stage embT[k][v] (f32, padded rows) in transient region
    {
        float* embT = (float*)(smem + SM_EMBT);
        for (int idx = tid; idx < Vdim * Hdim; idx += NTH) {
            int v = idx >> 8, k = idx & 255;          // coalesced emb reads
            embT[(size_t)k * ESTR + v] = emb[(size_t)v * Hdim + k];
        }
    }
    __syncthreads();
    // (2) P[v][o] = bias[o] + emb[v,:]·Wx[o,:]; thread owns column o = tid
    {
        const float* embT = (const float*)(smem + SM_EMBT);
        const int o = tid;
        const float bo = bias[o];
        const float4* wrow = (const float4*)(W + (size_t)o * (2 * Hdim));
        for (int vg = 0; vg < 4; ++vg) {
            unsigned long long acc[8];
#pragma unroll
            for (int i = 0; i < 8; ++i) acc[i] = pack2(0.f, 0.f);
            for (int k4 = 0; k4 < Hdim / 4; ++k4) {
                float4 wv = wrow[k4];
#pragma unroll
                for (int kk = 0; kk < 4; ++kk) {
                    int k = k4 * 4 + kk;
                    float w = (kk == 0) ? wv.x : (kk == 1) ? wv.y : (kk == 2) ? wv.z : wv.w;
                    unsigned long long wpair = pack2(w, w);
                    const ulonglong2* ep =
                        (const ulonglong2*)(embT + (size_t)k * ESTR + vg * 16);
                    ulonglong2 e0 = ep[0], e1 = ep[1], e2 = ep[2], e3 = ep[3];
                    ffma2(acc[0], wpair, e0.x); ffma2(acc[1], wpair, e0.y);
                    ffma2(acc[2], wpair, e1.x); ffma2(acc[3], wpair, e1.y);
                    ffma2(acc[4], wpair, e2.x); ffma2(acc[5], wpair, e2.y);
                    ffma2(acc[6], wpair, e3.x); ffma2(acc[7], wpair, e3.y);
                }
            }
#pragma unroll
            for (int i = 0; i < 8; ++i) {
                float lo = __uint_as_float((uint32_t)(acc[i] & 0xffffffffu));
                float hi = __uint_as_float((uint32_t)(acc[i] >> 32));
                int v0 = vg * 16 + 2 * i;
                Psm[(size_t)v0 * PSTR + o]       = bo + lo;
                Psm[(size_t)(v0 + 1) * PSTR + o] = bo + hi;
            }
        }
    }
    // (3) B fragments: WhT as n8k16 col-major fragments, straight from gmem.
    //     b0 = half2(Wh[n][k0], Wh[n][k0+1]), b1 = same at k0+8.
    uint32_t breg[4][16][2];
#pragma unroll
    for (int nt = 0; nt < 4; ++nt) {
        int n = wid * 32 + nt * 8 + g;
        const float* wr = W + (size_t)n * (2 * Hdim) + Hdim;   // Wh row n
#pragma unroll
        for (int c = 0; c < 16; ++c) {
            float2 lo = *(const float2*)&wr[2 * r + 16 * c];
            float2 hi = *(const float2*)&wr[2 * r + 8 + 16 * c];
            __half2 hlo = __floats2half2_rn(lo.x, lo.y);
            __half2 hhi = __floats2half2_rn(hi.x, hi.y);
            breg[nt][c][0] = *(uint32_t*)&hlo;
            breg[nt][c][1] = *(uint32_t*)&hhi;
        }
    }
    // (4) tokens -> [t][b] layout;  (5) h buf0 from h0 (fp16, padded rows)
    for (int idx = tid; idx < NB * Tdim; idx += NTH) {
        int b = idx >> 9, t = idx & 511;              // coalesced gmem reads
        toks[t * NB + b] = tokens[(size_t)(bbase + b) * Tdim + t];
    }
    {
        __half* hb = (__half*)(smem + SM_H0);
        for (int idx = tid; idx < NB * Hdim; idx += NTH) {
            int b = idx >> 8, k = idx & 255;
            hb[(size_t)b * HSTR + k] =
                __float2half_rn(h0[(size_t)(bbase + b) * Hdim + k]);
        }
    }
    __syncthreads();

    // ldmatrix lane address: row = lane&15, k-halfword offset = (lane>>4)*16B
    const uint32_t ldm_base =
        (uint32_t)((lane & 15) * (HSTR * 2) + (lane >> 4) * 16);
    const int o0 = wid * 32 + 2 * r;                  // thread's base output col
    float* const outcta = out + (size_t)bbase * Hdim;

    // ============== Recurrent loop ==============
    for (int t = 0; t < Tdim; ++t) {
        // tokens for this thread's two batches (broadcast loads)
        const int tk0 = toks[t * NB + g];
        const int tk1 = toks[t * NB + g + 8];

        // init accumulators with exact xproj: d = P[token][o..o+1]
        float d[4][4];
#pragma unroll
        for (int nt = 0; nt < 4; ++nt) {
            float2 p0 = *(const float2*)&Psm[(size_t)tk0 * PSTR + o0 + nt * 8];
            float2 p1 = *(const float2*)&Psm[(size_t)tk1 * PSTR + o0 + nt * 8];
            d[nt][0] = p0.x; d[nt][1] = p0.y;
            d[nt][2] = p1.x; d[nt][3] = p1.y;
        }

        // MMA chain over K=256 (16 chunks); A shared across the 4 n-tiles
        const uint32_t abuf = sbase + ((t & 1) ? SM_H1 : SM_H0) + ldm_base;
#pragma unroll
        for (int c = 0; c < 16; ++c) {
            uint32_t a[4];
            ldmx4(a[0], a[1], a[2], a[3], abuf + (uint32_t)c * 32);
            mma16816(d[0], a, breg[0][c][0], breg[0][c][1]);
            mma16816(d[1], a, breg[1][c][0], breg[1][c][1]);
            mma16816(d[2], a, breg[2][c][0], breg[2][c][1]);
            mma16816(d[3], a, breg[3][c][0], breg[3][c][1]);
        }

        // sigmoid + h_{t+1} store (must precede barrier)
        float s[4][4];
        __half* hn = (__half*)(smem + ((t & 1) ? SM_H0 : SM_H1));
#pragma unroll
        for (int nt = 0; nt < 4; ++nt) {
            s[nt][0] = sigmoidf(d[nt][0]);
            s[nt][1] = sigmoidf(d[nt][1]);
            s[nt][2] = sigmoidf(d[nt][2]);
            s[nt][3] = sigmoidf(d[nt][3]);
            int o = o0 + nt * 8;
            *(__half2*)&hn[(size_t)g * HSTR + o] =
                __floats2half2_rn(s[nt][0], s[nt][1]);
            *(__half2*)&hn[(size_t)(g + 8) * HSTR + o] =
                __floats2half2_rn(s[nt][2], s[nt][3]);
        }
        __syncthreads();

        // output stores after the barrier: drain overlaps next step's MMA
        float* outp = outcta + (size_t)t * (Bdim * Hdim);
#pragma unroll
        for (int nt = 0; nt < 4; ++nt) {
            int o = o0 + nt * 8;
            *(float2*)&outp[(size_t)g * Hdim + o]       = make_float2(s[nt][0], s[nt][1]);
            *(float2*)&outp[(size_t)(g + 8) * Hdim + o] = make_float2(s[nt][2], s[nt][3]);
        }
    }
}

// ---------------------------------------------------------------------------
// Harness entry.
// Inputs: tokens(i32 2048x512), h0(f32 2048x256), emb(f32 64x256),
//         W(f32 256x512), b(f32 256).  Output: f32 (512,2048,256)
// ---------------------------------------------------------------------------
extern "C" void kernel_launch(void* const* d_in, const int* in_sizes, int n_in,
                              void* d_out, int out_size) {
    const int*   tokens = (const int*)d_in[0];
    const float* h0     = (const float*)d_in[1];
    const float* emb    = (const float*)d_in[2];
    const float* W      = (const float*)d_in[3];
    const float* bias   = (const float*)d_in[4];
    float*       out    = (float*)d_out;
    (void)in_sizes; (void)n_in; (void)out_size;

    cudaFuncSetAttribute(k_rnn, cudaFuncAttributeMaxDynamicSharedMemorySize, SMEM_TOTAL);
    k_rnn<<<Bdim / NB, NTH, SMEM_TOTAL>>>(tokens, h0, emb, W, bias, out);
}

// round 8
// speedup vs baseline: 1.1304x; 1.1211x over previous
#include <cuda_runtime.h>
#include <cuda_fp16.h>
#include <cstdint>

#define Hdim 256
#define Bdim 2048
#define Tdim 512
#define Vdim 64
#define NB   16          // batches per CTA -> 128 CTAs
#define NTH  256         // 8 warps
#define HSTR 264         // h row stride in halfs (528B)
#define PSTR 266         // P row stride in floats
#define ESTR 68          // embT row stride in floats

// ---- shared memory layout (bytes) ----
#define SM_P    0                      // P[64][PSTR] f32 = 68096
#define SM_H0   68096                  // h buf0: 16 x 264 halfs = 8448
#define SM_H1   76544                  // h buf1: 8448
#define SM_TOK  84992                  // tokens [512][16] int = 32768
#define SM_MBAR 117760                 // mbarrier (8B, padded to 128)
#define SM_EMBT 117888                 // transient embT f32 [256][ESTR]
#define SMEM_TOTAL (117888 + 69632)    // 187520

// ---------------------------------------------------------------------------
__device__ __forceinline__ uint32_t smem_u32(const void* p) {
    uint32_t a;
    asm("{ .reg .u64 t; cvta.to.shared.u64 t, %1; cvt.u32.u64 %0, t; }"
        : "=r"(a) : "l"(p));
    return a;
}
// sigmoid via single-MUFU tanh: s = 0.5*tanh(0.5x) + 0.5
__device__ __forceinline__ float sigmoid_t(float x) {
    float t;
    asm("tanh.approx.f32 %0, %1;" : "=f"(t) : "f"(0.5f * x));
    return fmaf(0.5f, t, 0.5f);
}
__device__ __forceinline__ void ffma2(unsigned long long& d,
                                      unsigned long long a, unsigned long long b) {
    asm("fma.rn.f32x2 %0, %1, %2, %0;" : "+l"(d) : "l"(a), "l"(b));
}
__device__ __forceinline__ unsigned long long pack2(float lo, float hi) {
    unsigned long long r;
    asm("mov.b64 %0, {%1, %2};" : "=l"(r) : "f"(lo), "f"(hi));
    return r;
}
__device__ __forceinline__ void mma16816(float* d, const uint32_t* a,
                                         uint32_t b0, uint32_t b1) {
    asm volatile(
        "mma.sync.aligned.m16n8k16.row.col.f32.f16.f16.f32 "
        "{%0,%1,%2,%3}, {%4,%5,%6,%7}, {%8,%9}, {%0,%1,%2,%3};"
        : "+f"(d[0]), "+f"(d[1]), "+f"(d[2]), "+f"(d[3])
        : "r"(a[0]), "r"(a[1]), "r"(a[2]), "r"(a[3]), "r"(b0), "r"(b1));
}
__device__ __forceinline__ void ldmx4(uint32_t& r0, uint32_t& r1,
                                      uint32_t& r2, uint32_t& r3, uint32_t addr) {
    asm volatile(
        "ldmatrix.sync.aligned.m8n8.x4.shared.b16 {%0,%1,%2,%3}, [%4];"
        : "=r"(r0), "=r"(r1), "=r"(r2), "=r"(r3) : "r"(addr));
}
// mbarrier: arrive (release.cta) after STS; parity wait before consuming.
#define MBAR_INIT(mb, c) asm volatile("mbarrier.init.shared.b64 [%0], %1;" \
                                      :: "r"(mb), "r"(c) : "memory")
#define MBAR_ARRIVE(mb)  asm volatile("mbarrier.arrive.shared.b64 _, [%0];" \
                                      :: "r"(mb) : "memory")
__device__ __forceinline__ void mbar_wait(uint32_t mb, uint32_t parity) {
    asm volatile(
        "{ .reg .pred P;\n\t"
        "W_%=:\n\t"
        "mbarrier.try_wait.parity.acquire.cta.shared::cta.b64 P, [%0], %1, 0x989680;\n\t"
        "@P bra.uni D_%=;\n\t"
        "bra.uni W_%=;\n\t"
        "D_%=: }"
        :: "r"(mb), "r"(parity) : "memory");
}

// ---------------------------------------------------------------------------
// Persistent RNN: CTA owns 16 batch chains for 512 steps.
// D[16 batch, 256 out] = h[16,256] x WhT; warp w owns outputs [32w,32w+32)
// (breg register-resident, 128 regs). Split-phase mbarrier sync: warps
// dephase so MUFU sigmoid overlaps HMMA across warps; STG + P-loads live
// in the post-arrive shadow.
// ---------------------------------------------------------------------------
__global__ __launch_bounds__(NTH, 1)
void k_rnn(const int* __restrict__ tokens,
           const float* __restrict__ h0,
           const float* __restrict__ emb,
           const float* __restrict__ W,
           const float* __restrict__ bias,
           float* __restrict__ out) {
    extern __shared__ char smem[];
    const uint32_t sbase = smem_u32(smem);
    float* Psm  = (float*)(smem + SM_P);
    int*   toks = (int*)(smem + SM_TOK);
    const uint32_t mbar = sbase + SM_MBAR;

    const int tid  = threadIdx.x;
    const int wid  = tid >> 5;
    const int lane = tid & 31;
    const int g    = lane >> 2;     // 0..7
    const int r    = lane & 3;      // 0..3
    const int bbase = blockIdx.x * NB;

    // ============== Prologue ==============
    {
        float* embT = (float*)(smem + SM_EMBT);
        for (int idx = tid; idx < Vdim * Hdim; idx += NTH) {
            int v = idx >> 8, k = idx & 255;
            embT[(size_t)k * ESTR + v] = emb[(size_t)v * Hdim + k];
        }
    }
    __syncthreads();
    {   // P[v][o] = bias[o] + emb[v,:]·Wx[o,:]; thread owns column o = tid
        const float* embT = (const float*)(smem + SM_EMBT);
        const int o = tid;
        const float bo = bias[o];
        const float4* wrow = (const float4*)(W + (size_t)o * (2 * Hdim));
        for (int vg = 0; vg < 4; ++vg) {
            unsigned long long acc[8];
#pragma unroll
            for (int i = 0; i < 8; ++i) acc[i] = pack2(0.f, 0.f);
            for (int k4 = 0; k4 < Hdim / 4; ++k4) {
                float4 wv = wrow[k4];
#pragma unroll
                for (int kk = 0; kk < 4; ++kk) {
                    int k = k4 * 4 + kk;
                    float w = (kk == 0) ? wv.x : (kk == 1) ? wv.y : (kk == 2) ? wv.z : wv.w;
                    unsigned long long wpair = pack2(w, w);
                    const ulonglong2* ep =
                        (const ulonglong2*)(embT + (size_t)k * ESTR + vg * 16);
                    ulonglong2 e0 = ep[0], e1 = ep[1], e2 = ep[2], e3 = ep[3];
                    ffma2(acc[0], wpair, e0.x); ffma2(acc[1], wpair, e0.y);
                    ffma2(acc[2], wpair, e1.x); ffma2(acc[3], wpair, e1.y);
                    ffma2(acc[4], wpair, e2.x); ffma2(acc[5], wpair, e2.y);
                    ffma2(acc[6], wpair, e3.x); ffma2(acc[7], wpair, e3.y);
                }
            }
#pragma unroll
            for (int i = 0; i < 8; ++i) {
                float lo = __uint_as_float((uint32_t)(acc[i] & 0xffffffffu));
                float hi = __uint_as_float((uint32_t)(acc[i] >> 32));
                int v0 = vg * 16 + 2 * i;
                Psm[(size_t)v0 * PSTR + o]       = bo + lo;
                Psm[(size_t)(v0 + 1) * PSTR + o] = bo + hi;
            }
        }
    }
    // B fragments: WhT n8k16 col-major fragments straight from gmem
    uint32_t breg[4][16][2];
#pragma unroll
    for (int nt = 0; nt < 4; ++nt) {
        int n = wid * 32 + nt * 8 + g;
        const float* wr = W + (size_t)n * (2 * Hdim) + Hdim;
#pragma unroll
        for (int c = 0; c < 16; ++c) {
            float2 lo = *(const float2*)&wr[2 * r + 16 * c];
            float2 hi = *(const float2*)&wr[2 * r + 8 + 16 * c];
            __half2 hlo = __floats2half2_rn(lo.x, lo.y);
            __half2 hhi = __floats2half2_rn(hi.x, hi.y);
            breg[nt][c][0] = *(uint32_t*)&hlo;
            breg[nt][c][1] = *(uint32_t*)&hhi;
        }
    }
    for (int idx = tid; idx < NB * Tdim; idx += NTH) {
        int b = idx >> 9, t = idx & 511;
        toks[t * NB + b] = tokens[(size_t)(bbase + b) * Tdim + t];
    }
    {
        __half* hb = (__half*)(smem + SM_H0);
        for (int idx = tid; idx < NB * Hdim; idx += NTH) {
            int b = idx >> 8, k = idx & 255;
            hb[(size_t)b * HSTR + k] =
                __float2half_rn(h0[(size_t)(bbase + b) * Hdim + k]);
        }
    }
    if (tid == 0) MBAR_INIT(mbar, NTH);
    __syncthreads();
    MBAR_ARRIVE(mbar);       // completes phase 0: h(0) published

    const uint32_t ldm_base =
        (uint32_t)((lane & 15) * (HSTR * 2) + (lane >> 4) * 16);
    const int o0 = wid * 32 + 2 * r;
    float* const outcta = out + (size_t)bbase * Hdim;

    // ============== Recurrent loop ==============
    for (int t = 0; t < Tdim; ++t) {
        // wait for phase t (h(t) stores from all threads visible)
        mbar_wait(mbar, (uint32_t)(t & 1));

        const int tk0 = toks[t * NB + g];
        const int tk1 = toks[t * NB + g + 8];
        float d[4][4];
#pragma unroll
        for (int nt = 0; nt < 4; ++nt) {
            float2 p0 = *(const float2*)&Psm[(size_t)tk0 * PSTR + o0 + nt * 8];
            float2 p1 = *(const float2*)&Psm[(size_t)tk1 * PSTR + o0 + nt * 8];
            d[nt][0] = p0.x; d[nt][1] = p0.y;
            d[nt][2] = p1.x; d[nt][3] = p1.y;
        }

        const uint32_t abuf = sbase + ((t & 1) ? SM_H1 : SM_H0) + ldm_base;
#pragma unroll
        for (int c = 0; c < 16; ++c) {
            uint32_t a[4];
            ldmx4(a[0], a[1], a[2], a[3], abuf + (uint32_t)c * 32);
            mma16816(d[0], a, breg[0][c][0], breg[0][c][1]);
            mma16816(d[1], a, breg[1][c][0], breg[1][c][1]);
            mma16816(d[2], a, breg[2][c][0], breg[2][c][1]);
            mma16816(d[3], a, breg[3][c][0], breg[3][c][1]);
        }

        // sigmoid + h_{t+1} STS, then arrive (release) -> phase t+1
        float s[4][4];
        __half* hn = (__half*)(smem + ((t & 1) ? SM_H0 : SM_H1));
#pragma unroll
        for (int nt = 0; nt < 4; ++nt) {
            s[nt][0] = sigmoid_t(d[nt][0]);
            s[nt][1] = sigmoid_t(d[nt][1]);
            s[nt][2] = sigmoid_t(d[nt][2]);
            s[nt][3] = sigmoid_t(d[nt][3]);
            int o = o0 + nt * 8;
            *(__half2*)&hn[(size_t)g * HSTR + o] =
                __floats2half2_rn(s[nt][0], s[nt][1]);
            *(__half2*)&hn[(size_t)(g + 8) * HSTR + o] =
                __floats2half2_rn(s[nt][2], s[nt][3]);
        }
        MBAR_ARRIVE(mbar);

        // output drain in the post-arrive shadow
        float* outp = outcta + (size_t)t * (Bdim * Hdim);
#pragma unroll
        for (int nt = 0; nt < 4; ++nt) {
            int o = o0 + nt * 8;
            *(float2*)&outp[(size_t)g * Hdim + o]       = make_float2(s[nt][0], s[nt][1]);
            *(float2*)&outp[(size_t)(g + 8) * Hdim + o] = make_float2(s[nt][2], s[nt][3]);
        }
    }
}

// ---------------------------------------------------------------------------
// Harness entry.
// Inputs: tokens(i32 2048x512), h0(f32 2048x256), emb(f32 64x256),
//         W(f32 256x512), b(f32 256).  Output: f32 (512,2048,256)
// ---------------------------------------------------------------------------
extern "C" void kernel_launch(void* const* d_in, const int* in_sizes, int n_in,
                              void* d_out, int out_size) {
    const int*   tokens = (const int*)d_in[0];
    const float* h0     = (const float*)d_in[1];
    const float* emb    = (const float*)d_in[2];
    const float* W      = (const float*)d_in[3];
    const float* bias   = (const float*)d_in[4];
    float*       out    = (float*)d_out;
    (void)in_sizes; (void)n_in; (void)out_size;

    cudaFuncSetAttribute(k_rnn, cudaFuncAttributeMaxDynamicSharedMemorySize, SMEM_TOTAL);
    k_rnn<<<Bdim / NB, NTH, SMEM_TOTAL>>>(tokens, h0, emb, W, bias, out);
}

// round 10
// speedup vs baseline: 1.2237x; 1.0826x over previous
#include <cuda_runtime.h>
#include <cuda_fp16.h>
#include <cstdint>

#define Hdim 256
#define Bdim 2048
#define Tdim 512
#define Vdim 64
#define NB   16          // batches per CTA -> 128 CTAs
#define NTH  512         // 16 warps, each owns 16 outputs (2 n8 tiles)
#define HSTR 264         // h row stride in halfs (528B)
#define PSTR 266         // P row stride in floats
#define ESTR 68          // embT row stride in floats

// ---- shared memory layout (bytes) ----
#define SM_P    0                      // P[64][PSTR] f32 = 68096
#define SM_H0   68096                  // h buf0: 16 x 264 halfs = 8448
#define SM_H1   76544                  // h buf1: 8448
#define SM_TOK  84992                  // tokens [512][16] int = 32768
#define SM_MBAR 117760                 // mbarrier
#define SM_EMBT 117888                 // transient embT f32 [256][ESTR]
#define SMEM_TOTAL (117888 + 69632)    // 187520

// ---------------------------------------------------------------------------
__device__ __forceinline__ uint32_t smem_u32(const void* p) {
    uint32_t a;
    asm("{ .reg .u64 t; cvta.to.shared.u64 t, %1; cvt.u32.u64 %0, t; }"
        : "=r"(a) : "l"(p));
    return a;
}
// sigmoid via single-MUFU tanh: s = 0.5*tanh(0.5x) + 0.5
__device__ __forceinline__ float sigmoid_t(float x) {
    float t;
    asm("tanh.approx.f32 %0, %1;" : "=f"(t) : "f"(0.5f * x));
    return fmaf(0.5f, t, 0.5f);
}
__device__ __forceinline__ void ffma2(unsigned long long& d,
                                      unsigned long long a, unsigned long long b) {
    asm("fma.rn.f32x2 %0, %1, %2, %0;" : "+l"(d) : "l"(a), "l"(b));
}
__device__ __forceinline__ unsigned long long pack2(float lo, float hi) {
    unsigned long long r;
    asm("mov.b64 %0, {%1, %2};" : "=l"(r) : "f"(lo), "f"(hi));
    return r;
}
__device__ __forceinline__ void mma16816(float* d, const uint32_t* a,
                                         uint32_t b0, uint32_t b1) {
    asm volatile(
        "mma.sync.aligned.m16n8k16.row.col.f32.f16.f16.f32 "
        "{%0,%1,%2,%3}, {%4,%5,%6,%7}, {%8,%9}, {%0,%1,%2,%3};"
        : "+f"(d[0]), "+f"(d[1]), "+f"(d[2]), "+f"(d[3])
        : "r"(a[0]), "r"(a[1]), "r"(a[2]), "r"(a[3]), "r"(b0), "r"(b1));
}
__device__ __forceinline__ void ldmx4(uint32_t& r0, uint32_t& r1,
                                      uint32_t& r2, uint32_t& r3, uint32_t addr) {
    asm volatile(
        "ldmatrix.sync.aligned.m8n8.x4.shared.b16 {%0,%1,%2,%3}, [%4];"
        : "=r"(r0), "=r"(r1), "=r"(r2), "=r"(r3) : "r"(addr));
}
#define MBAR_INIT(mb, c) asm volatile("mbarrier.init.shared.b64 [%0], %1;" \
                                      :: "r"(mb), "r"(c) : "memory")
#define MBAR_ARRIVE(mb)  asm volatile("mbarrier.arrive.shared.b64 _, [%0];" \
                                      :: "r"(mb) : "memory")
__device__ __forceinline__ void mbar_wait(uint32_t mb, uint32_t parity) {
    asm volatile(
        "{ .reg .pred P;\n\t"
        "W_%=:\n\t"
        "mbarrier.try_wait.parity.acquire.cta.shared::cta.b64 P, [%0], %1, 0x989680;\n\t"
        "@P bra.uni D_%=;\n\t"
        "bra.uni W_%=;\n\t"
        "D_%=: }"
        :: "r"(mb), "r"(parity) : "memory");
}

// ---------------------------------------------------------------------------
// Persistent RNN: CTA owns 16 batch chains for 512 steps.
// D[16 batch, 256 out] = h[16,256] x WhT; warp w owns outputs [16w, 16w+16)
// (2 n8 tiles, breg register-resident = 64 regs). Single mbarrier (every
// thread arrives AND waits -> skew-free). Accumulator chains SPLIT: chunks
// 0-7 accumulate into dA, 8-15 into dB (independent 8-deep HMMA chains,
// interleaved for ILP), summed in the epilogue.
// ---------------------------------------------------------------------------
__global__ __launch_bounds__(NTH, 1)
void k_rnn(const int* __restrict__ tokens,
           const float* __restrict__ h0,
           const float* __restrict__ emb,
           const float* __restrict__ W,
           const float* __restrict__ bias,
           float* __restrict__ out) {
    extern __shared__ char smem[];
    const uint32_t sbase = smem_u32(smem);
    float* Psm  = (float*)(smem + SM_P);
    int*   toks = (int*)(smem + SM_TOK);
    const uint32_t mbar = sbase + SM_MBAR;

    const int tid  = threadIdx.x;
    const int wid  = tid >> 5;
    const int lane = tid & 31;
    const int g    = lane >> 2;     // 0..7
    const int r    = lane & 3;      // 0..3
    const int bbase = blockIdx.x * NB;

    // ============== Prologue ==============
    {
        float* embT = (float*)(smem + SM_EMBT);
        for (int idx = tid; idx < Vdim * Hdim; idx += NTH) {
            int v = idx >> 8, k = idx & 255;
            embT[(size_t)k * ESTR + v] = emb[(size_t)v * Hdim + k];
        }
    }
    __syncthreads();
    {   // P[v][o] = bias[o] + emb[v,:]·Wx[o,:]; thread: o = tid&255, 2 v-groups
        const float* embT = (const float*)(smem + SM_EMBT);
        const int o = tid & 255;
        const int vg0 = (tid >> 8) * 2;
        const float bo = bias[o];
        const float4* wrow = (const float4*)(W + (size_t)o * (2 * Hdim));
        for (int vg = vg0; vg < vg0 + 2; ++vg) {
            unsigned long long acc[8];
#pragma unroll
            for (int i = 0; i < 8; ++i) acc[i] = pack2(0.f, 0.f);
            for (int k4 = 0; k4 < Hdim / 4; ++k4) {
                float4 wv = wrow[k4];
#pragma unroll
                for (int kk = 0; kk < 4; ++kk) {
                    int k = k4 * 4 + kk;
                    float w = (kk == 0) ? wv.x : (kk == 1) ? wv.y : (kk == 2) ? wv.z : wv.w;
                    unsigned long long wpair = pack2(w, w);
                    const ulonglong2* ep =
                        (const ulonglong2*)(embT + (size_t)k * ESTR + vg * 16);
                    ulonglong2 e0 = ep[0], e1 = ep[1], e2 = ep[2], e3 = ep[3];
                    ffma2(acc[0], wpair, e0.x); ffma2(acc[1], wpair, e0.y);
                    ffma2(acc[2], wpair, e1.x); ffma2(acc[3], wpair, e1.y);
                    ffma2(acc[4], wpair, e2.x); ffma2(acc[5], wpair, e2.y);
                    ffma2(acc[6], wpair, e3.x); ffma2(acc[7], wpair, e3.y);
                }
            }
#pragma unroll
            for (int i = 0; i < 8; ++i) {
                float lo = __uint_as_float((uint32_t)(acc[i] & 0xffffffffu));
                float hi = __uint_as_float((uint32_t)(acc[i] >> 32));
                int v0 = vg * 16 + 2 * i;
                Psm[(size_t)v0 * PSTR + o]       = bo + lo;
                Psm[(size_t)(v0 + 1) * PSTR + o] = bo + hi;
            }
        }
    }
    // B fragments: warp owns outputs [16w, 16w+16) -> 2 n8 tiles
    uint32_t breg[2][16][2];
#pragma unroll
    for (int nt = 0; nt < 2; ++nt) {
        int n = wid * 16 + nt * 8 + g;
        const float* wr = W + (size_t)n * (2 * Hdim) + Hdim;
#pragma unroll
        for (int c = 0; c < 16; ++c) {
            float2 lo = *(const float2*)&wr[2 * r + 16 * c];
            float2 hi = *(const float2*)&wr[2 * r + 8 + 16 * c];
            __half2 hlo = __floats2half2_rn(lo.x, lo.y);
            __half2 hhi = __floats2half2_rn(hi.x, hi.y);
            breg[nt][c][0] = *(uint32_t*)&hlo;
            breg[nt][c][1] = *(uint32_t*)&hhi;
        }
    }
    for (int idx = tid; idx < NB * Tdim; idx += NTH) {
        int b = idx >> 9, t = idx & 511;
        toks[t * NB + b] = tokens[(size_t)(bbase + b) * Tdim + t];
    }
    {
        __half* hb = (__half*)(smem + SM_H0);
        for (int idx = tid; idx < NB * Hdim; idx += NTH) {
            int b = idx >> 8, k = idx & 255;
            hb[(size_t)b * HSTR + k] =
                __float2half_rn(h0[(size_t)(bbase + b) * Hdim + k]);
        }
    }
    if (tid == 0) MBAR_INIT(mbar, NTH);
    __syncthreads();
    MBAR_ARRIVE(mbar);       // phase 0: h(0) published

    const uint32_t ldm_base =
        (uint32_t)((lane & 15) * (HSTR * 2) + (lane >> 4) * 16);
    const int o0 = wid * 16 + 2 * r;
    float* const outcta = out + (size_t)bbase * Hdim;

    // ============== Recurrent loop ==============
    for (int t = 0; t < Tdim; ++t) {
        // P/token prefetch (stable regions; independent of the wait)
        const int tk0 = toks[t * NB + g];
        const int tk1 = toks[t * NB + g + 8];
        float dA[2][4], dB[2][4];
#pragma unroll
        for (int nt = 0; nt < 2; ++nt) {
            float2 p0 = *(const float2*)&Psm[(size_t)tk0 * PSTR + o0 + nt * 8];
            float2 p1 = *(const float2*)&Psm[(size_t)tk1 * PSTR + o0 + nt * 8];
            dA[nt][0] = p0.x; dA[nt][1] = p0.y;
            dA[nt][2] = p1.x; dA[nt][3] = p1.y;
            dB[nt][0] = 0.f;  dB[nt][1] = 0.f;
            dB[nt][2] = 0.f;  dB[nt][3] = 0.f;
        }

        mbar_wait(mbar, (uint32_t)(t & 1));
        const uint32_t abuf = sbase + ((t & 1) ? SM_H1 : SM_H0) + ldm_base;

        // two independent 8-deep chains per n-tile, interleaved for ILP
#pragma unroll
        for (int cc = 0; cc < 8; ++cc) {
            uint32_t a0[4], a1[4];
            ldmx4(a0[0], a0[1], a0[2], a0[3], abuf + (uint32_t)cc * 32);
            ldmx4(a1[0], a1[1], a1[2], a1[3], abuf + (uint32_t)(cc + 8) * 32);
            mma16816(dA[0], a0, breg[0][cc][0], breg[0][cc][1]);
            mma16816(dB[0], a1, breg[0][cc + 8][0], breg[0][cc + 8][1]);
            mma16816(dA[1], a0, breg[1][cc][0], breg[1][cc][1]);
            mma16816(dB[1], a1, breg[1][cc + 8][0], breg[1][cc + 8][1]);
        }

        // fold chains, sigmoid, STS h_{t+1}, arrive
        float s[2][4];
        __half* hn = (__half*)(smem + ((t & 1) ? SM_H0 : SM_H1));
#pragma unroll
        for (int nt = 0; nt < 2; ++nt) {
            s[nt][0] = sigmoid_t(dA[nt][0] + dB[nt][0]);
            s[nt][1] = sigmoid_t(dA[nt][1] + dB[nt][1]);
            s[nt][2] = sigmoid_t(dA[nt][2] + dB[nt][2]);
            s[nt][3] = sigmoid_t(dA[nt][3] + dB[nt][3]);
            int o = o0 + nt * 8;
            *(__half2*)&hn[(size_t)g * HSTR + o] =
                __floats2half2_rn(s[nt][0], s[nt][1]);
            *(__half2*)&hn[(size_t)(g + 8) * HSTR + o] =
                __floats2half2_rn(s[nt][2], s[nt][3]);
        }
        MBAR_ARRIVE(mbar);

        // output drain in the post-arrive shadow
        float* outp = outcta + (size_t)t * (Bdim * Hdim);
#pragma unroll
        for (int nt = 0; nt < 2; ++nt) {
            int o = o0 + nt * 8;
            *(float2*)&outp[(size_t)g * Hdim + o]       = make_float2(s[nt][0], s[nt][1]);
            *(float2*)&outp[(size_t)(g + 8) * Hdim + o] = make_float2(s[nt][2], s[nt][3]);
        }
    }
}

// ---------------------------------------------------------------------------
// Harness entry.
// Inputs: tokens(i32 2048x512), h0(f32 2048x256), emb(f32 64x256),
//         W(f32 256x512), b(f32 256).  Output: f32 (512,2048,256)
// ---------------------------------------------------------------------------
extern "C" void kernel_launch(void* const* d_in, const int* in_sizes, int n_in,
                              void* d_out, int out_size) {
    const int*   tokens = (const int*)d_in[0];
    const float* h0     = (const float*)d_in[1];
    const float* emb    = (const float*)d_in[2];
    const float* W      = (const float*)d_in[3];
    const float* bias   = (const float*)d_in[4];
    float*       out    = (float*)d_out;
    (void)in_sizes; (void)n_in; (void)out_size;

    cudaFuncSetAttribute(k_rnn, cudaFuncAttributeMaxDynamicSharedMemorySize, SMEM_TOTAL);
    k_rnn<<<Bdim / NB, NTH, SMEM_TOTAL>>>(tokens, h0, emb, W, bias, out);
}